// round 15
// baseline (speedup 1.0000x reference)
#include <cuda_runtime.h>

// GRUExtractor: 2-layer GRU, B=4096, T=256, I=16, H=40, fp32.
// R15: R14 + (a) biases folded into Phase-A accumulator init, row unroll 7;
//      (b) Phase B float4 tasks (280/slot), warp-aligned layer split;
//      (c) prepass 2 rows/thread, float2 stores, 2 t-groups.

#define HSZ 40
#define ISZ 16
#define TSZ 256
#define NB  4096
#define NR  14
#define SLOT_T 384
#define CTA_T  768
#define NGR 120

typedef unsigned long long u64;
typedef ulonglong2 u64x2;

__device__ float g_xg[(size_t)NB * TSZ * NGR];   // xg[b][t][gate_row] (incl bih0)

__device__ __forceinline__ u64 pk2(float lo, float hi) {
    u64 d; asm("mov.b64 %0,{%1,%2};" : "=l"(d) : "f"(lo), "f"(hi)); return d;
}
__device__ __forceinline__ void upk2(u64 d, float& a, float& b) {
    asm("mov.b64 {%0,%1},%2;" : "=f"(a), "=f"(b) : "l"(d));
}
__device__ __forceinline__ u64 ffma2(u64 a, u64 b, u64 c) {
    u64 d; asm("fma.rn.f32x2 %0,%1,%2,%3;" : "=l"(d) : "l"(a), "l"(b), "l"(c)); return d;
}
__device__ __forceinline__ u64 add2(u64 a, u64 b) {
    u64 d; asm("add.rn.f32x2 %0,%1,%2;" : "=l"(d) : "l"(a), "l"(b)); return d;
}
__device__ __forceinline__ float hsum2(u64 d) { float a, b; upk2(d, a, b); return a + b; }

__device__ __forceinline__ float sigm(float x) {
    return __fdividef(1.0f, 1.0f + __expf(-x));
}
__device__ __forceinline__ float tanh_f(float x) {
    return __fdividef(2.0f, 1.0f + __expf(-2.0f * x)) - 1.0f;
}
__device__ __forceinline__ float4 add4(float4 a, float4 b) {
    return make_float4(a.x + b.x, a.y + b.y, a.z + b.z, a.w + b.w);
}
__device__ __forceinline__ float gru_upd(float pre_r, float pre_z,
                                         float xn, float hn, float h) {
    float r_ = sigm(pre_r);
    float z_ = sigm(pre_z);
    float n_ = tanh_f(fmaf(r_, hn, xn));
    return fmaf(z_, h - n_, n_);
}

__device__ __forceinline__ void slot_bar(int slot) {
    asm volatile("bar.sync %0, %1;" :: "r"(slot + 1), "r"(SLOT_T) : "memory");
}

// ---------------- prepass: xg = Wih0 . x + bih0 ----------------
__global__ void __launch_bounds__(128, 8) xg_prepass(
    const float* __restrict__ x, const float* __restrict__ Wih0,
    const float* __restrict__ bih0)
{
    __shared__ __align__(16) float4 xs[TSZ * 4];
    const int b = blockIdx.x;
    const int tid = threadIdx.x;
    for (int i = tid; i < TSZ * 4; i += 128)
        xs[i] = ((const float4*)x)[b * (TSZ * 4) + i];

    const int grp = tid >> 6;                  // t parity group
    int m = tid & 63; if (m > 59) m = 59;      // dup lanes write same data
    const int gr0 = 2 * m;

    u64 w[16];
    const u64x2* w0 = (const u64x2*)(Wih0 + gr0 * ISZ);
    const u64x2* w1 = (const u64x2*)(Wih0 + (gr0 + 1) * ISZ);
    #pragma unroll
    for (int q = 0; q < 4; q++) {
        u64x2 v0 = w0[q]; w[2*q]     = v0.x; w[2*q+1]     = v0.y;
        u64x2 v1 = w1[q]; w[8 + 2*q] = v1.x; w[8 + 2*q+1] = v1.y;
    }
    const u64 bi0 = pk2(bih0[gr0], 0.0f);
    const u64 bi1 = pk2(bih0[gr0 + 1], 0.0f);
    __syncthreads();

    float* dst = g_xg + (size_t)b * TSZ * NGR + gr0;
    #pragma unroll 4
    for (int t = grp; t < TSZ; t += 2) {
        const u64x2* xp = (const u64x2*)&xs[t * 4];
        u64 a0 = bi0, a1 = 0ull, b0 = bi1, b1 = 0ull;
        #pragma unroll
        for (int q = 0; q < 4; q++) {
            u64x2 v = xp[q];
            a0 = ffma2(w[2*q],     v.x, a0);
            a1 = ffma2(w[2*q+1],   v.y, a1);
            b0 = ffma2(w[8+2*q],   v.x, b0);
            b1 = ffma2(w[8+2*q+1], v.y, b1);
        }
        float2 o;
        o.x = hsum2(add2(a0, a1));
        o.y = hsum2(add2(b0, b1));
        *(float2*)(dst + t * NGR) = o;
    }
}

// ---------------- main recurrent kernel ----------------
struct Slot {
    float h0[NR][HSZ];
    float h1[NR][HSZ];
    float pA[2][NR][NGR];         // L0 partials [half] (half0 incl bhh0)
    float pB[2][2][NR][NGR];      // L1 partials [mat][half] (half0 incl bias)
    float xb[2][NR][NGR];         // xg double buffer
};

__global__ void __launch_bounds__(CTA_T, 1) gru_main(
    const float* __restrict__ Whh0,
    const float* __restrict__ bhh0,
    const float* __restrict__ Wih1,
    const float* __restrict__ Whh1,
    const float* __restrict__ bih1,
    const float* __restrict__ bhh1,
    float* __restrict__ out)
{
    extern __shared__ __align__(16) char smraw[];
    Slot* sl = (Slot*)smraw;

    const int tid  = threadIdx.x;
    const int slot = tid / SLOT_T;
    const int r    = tid - slot * SLOT_T;
    Slot& S = sl[slot];
    const int base = (blockIdx.x * 2 + slot) * NR;

    // ---- roles: r<128 -> L0 (warp-uniform half); 128..383 -> L1 ----
    const bool isL0 = (r < 128);
    int half, mat = 0, gr0;
    const float* Wsrc;
    const float* Bsrc;
    if (isL0) {
        half = r >> 6;
        int m = r & 63; if (m > 59) m = 59;
        gr0 = 2 * m;
        Wsrc = Whh0;
        Bsrc = bhh0;
    } else {
        int i2 = r - 128;
        half = i2 >> 7;
        mat  = (i2 >> 6) & 1;
        int u = i2 & 63; if (u > 59) u = 59;
        gr0 = 2 * u;
        Wsrc = mat ? Whh1 : Wih1;
        Bsrc = mat ? bhh1 : bih1;
    }
    const int hofs = half * 20;

    // ---- register weights + bias-in-init (half0 only) ----
    u64 w[20];
    u64 bi0 = 0ull, bi1 = 0ull;
    {
        const u64x2* p0 = (const u64x2*)(Wsrc + gr0 * HSZ + hofs);
        const u64x2* p1 = (const u64x2*)(Wsrc + (gr0 + 1) * HSZ + hofs);
        #pragma unroll
        for (int q = 0; q < 5; q++) {
            u64x2 v0 = p0[q]; w[2*q]      = v0.x; w[2*q+1]      = v0.y;
            u64x2 v1 = p1[q]; w[10 + 2*q] = v1.x; w[10 + 2*q+1] = v1.y;
        }
        if (half == 0) {
            bi0 = pk2(Bsrc[gr0], 0.0f);
            bi1 = pk2(Bsrc[gr0 + 1], 0.0f);
        }
    }

    // ---- init: zero h, stage xg(t=0) ----
    for (int e = r; e < NR * HSZ; e += SLOT_T) {
        S.h0[e / HSZ][e % HSZ] = 0.0f;
        S.h1[e / HSZ][e % HSZ] = 0.0f;
    }
    for (int idx = r; idx < NR * 30; idx += SLOT_T) {
        int row = idx / 30, c = idx - row * 30;
        int grow = base + row; if (grow > NB - 1) grow = NB - 1;
        ((float4*)S.xb[0][row])[c] =
            ((const float4*)g_xg)[((size_t)grow * TSZ) * 30 + c];
    }
    __syncthreads();

    // ---- supersteps: L0 computes t=s, L1 computes t=s-1 ----
    for (int s = 0; s <= TSZ; ++s) {
        // register prefetch of xg(s+1)
        float4 pf0, pf1;
        int pi0 = -1, pi1 = -1;
        const int s1 = s + 1;
        if (s1 < TSZ) {
            if (r < NR * 30) {
                int row = r / 30, c = r - row * 30;
                int grow = base + row; if (grow > NB - 1) grow = NB - 1;
                pf0 = ((const float4*)g_xg)[((size_t)grow * TSZ + s1) * 30 + c];
                pi0 = r;
            }
            int idx = r + SLOT_T;
            if (idx < NR * 30) {
                int row = idx / 30, c = idx - row * 30;
                int grow = base + row; if (grow > NB - 1) grow = NB - 1;
                pf1 = ((const float4*)g_xg)[((size_t)grow * TSZ + s1) * 30 + c];
                pi1 = idx;
            }
        }

        // ===== PHASE A: partial h-dots (bias folded into accum init) =====
        const bool act = isL0 ? (s < TSZ) : (s >= 1);
        if (act) {
            const float (*hsrc)[HSZ] = (isL0 || mat == 0) ? S.h0 : S.h1;
            float* pout = isL0 ? &S.pA[half][0][0] : &S.pB[mat][half][0][0];
            #pragma unroll 7
            for (int row = 0; row < NR; ++row) {
                const u64x2* hp = (const u64x2*)(&hsrc[row][hofs]);
                u64 a0 = bi0, a1 = 0ull, b0 = bi1, b1 = 0ull;
                #pragma unroll
                for (int q = 0; q < 5; q++) {
                    u64x2 v = hp[q];
                    a0 = ffma2(w[2*q],        v.x, a0);
                    a1 = ffma2(w[2*q+1],      v.y, a1);
                    b0 = ffma2(w[10 + 2*q],   v.x, b0);
                    b1 = ffma2(w[10 + 2*q+1], v.y, b1);
                }
                float2 pr;
                pr.x = hsum2(add2(a0, a1));
                pr.y = hsum2(add2(b0, b1));
                *(float2*)&pout[row * NGR + gr0] = pr;
            }
        }

        // commit xg prefetch to other parity
        if (pi0 >= 0) ((float4*)&S.xb[s1 & 1][0][0])[pi0] = pf0;
        if (pi1 >= 0) ((float4*)&S.xb[s1 & 1][0][0])[pi1] = pf1;
        slot_bar(slot);

        // ===== PHASE B: float4 tasks, warp-aligned layer split =====
        // L0: r in [0,140); L1: r in [192,332). 10 float4 groups per row.
        if (r < 140) {
            if (s < TSZ) {
                int row = r / 10, jq = (r - row * 10) * 4;
                const float* q0 = &S.pA[0][row][0];
                const float* q1 = &S.pA[1][row][0];
                const float* xv = S.xb[s & 1][row];
                float4 hr = add4(*(const float4*)(q0 + jq),
                                 *(const float4*)(q1 + jq));
                float4 hz = add4(*(const float4*)(q0 + 40 + jq),
                                 *(const float4*)(q1 + 40 + jq));
                float4 hn = add4(*(const float4*)(q0 + 80 + jq),
                                 *(const float4*)(q1 + 80 + jq));
                float4 xr = *(const float4*)(xv + jq);
                float4 xz = *(const float4*)(xv + 40 + jq);
                float4 xn = *(const float4*)(xv + 80 + jq);
                float4 h  = *(float4*)&S.h0[row][jq];
                h.x = gru_upd(xr.x + hr.x, xz.x + hz.x, xn.x, hn.x, h.x);
                h.y = gru_upd(xr.y + hr.y, xz.y + hz.y, xn.y, hn.y, h.y);
                h.z = gru_upd(xr.z + hr.z, xz.z + hz.z, xn.z, hn.z, h.z);
                h.w = gru_upd(xr.w + hr.w, xz.w + hz.w, xn.w, hn.w, h.w);
                *(float4*)&S.h0[row][jq] = h;
            }
        } else if (r >= 192 && r < 332) {
            if (s >= 1) {
                int t = r - 192;
                int row = t / 10, jq = (t - row * 10) * 4;
                const float* i0 = &S.pB[0][0][row][0];
                const float* i1 = &S.pB[0][1][row][0];
                const float* g0 = &S.pB[1][0][row][0];
                const float* g1 = &S.pB[1][1][row][0];
                float4 rr = add4(add4(*(const float4*)(i0 + jq),
                                      *(const float4*)(i1 + jq)),
                                 add4(*(const float4*)(g0 + jq),
                                      *(const float4*)(g1 + jq)));
                float4 zz = add4(add4(*(const float4*)(i0 + 40 + jq),
                                      *(const float4*)(i1 + 40 + jq)),
                                 add4(*(const float4*)(g0 + 40 + jq),
                                      *(const float4*)(g1 + 40 + jq)));
                float4 in_ = add4(*(const float4*)(i0 + 80 + jq),
                                  *(const float4*)(i1 + 80 + jq));
                float4 hn  = add4(*(const float4*)(g0 + 80 + jq),
                                  *(const float4*)(g1 + 80 + jq));
                float4 h = *(float4*)&S.h1[row][jq];
                h.x = gru_upd(rr.x, zz.x, in_.x, hn.x, h.x);
                h.y = gru_upd(rr.y, zz.y, in_.y, hn.y, h.y);
                h.z = gru_upd(rr.z, zz.z, in_.z, hn.z, h.z);
                h.w = gru_upd(rr.w, zz.w, in_.w, hn.w, h.w);
                *(float4*)&S.h1[row][jq] = h;
            }
        }
        slot_bar(slot);
    }

    // ---- write final layer-1 hidden state (clamped rows dup, benign) ----
    for (int e = r; e < NR * HSZ; e += SLOT_T) {
        int row = e / HSZ, jj = e % HSZ;
        int grow = base + row; if (grow > NB - 1) grow = NB - 1;
        out[grow * HSZ + jj] = S.h1[row][jj];
    }
}

extern "C" void kernel_launch(void* const* d_in, const int* in_sizes, int n_in,
                              void* d_out, int out_size) {
    const float* x    = (const float*)d_in[0];
    const float* Wih0 = (const float*)d_in[1];
    const float* Whh0 = (const float*)d_in[2];
    const float* bih0 = (const float*)d_in[3];
    const float* bhh0 = (const float*)d_in[4];
    const float* Wih1 = (const float*)d_in[5];
    const float* Whh1 = (const float*)d_in[6];
    const float* bih1 = (const float*)d_in[7];
    const float* bhh1 = (const float*)d_in[8];
    float* out = (float*)d_out;

    xg_prepass<<<NB, 128>>>(x, Wih0, bih0);

    const int smem_bytes = 2 * (int)sizeof(Slot);
    cudaFuncSetAttribute(gru_main,
                         cudaFuncAttributeMaxDynamicSharedMemorySize, smem_bytes);
    gru_main<<<148, CTA_T, smem_bytes>>>(Whh0, bhh0, Wih1, Whh1, bih1, bhh1, out);
}